// round 12
// baseline (speedup 1.0000x reference)
#include <cuda_runtime.h>
#include <cuda_bf16.h>
#include <mma.h>
#include <math.h>
#include <stdint.h>

using namespace nvcuda;

// ---------------------------------------------------------------------------
// SingleToPairwise — WMMA bf16-split GEMM (1-sync cp.async pipeline) +
// tensor-core final projection.
// Split precision: x = hi + lo (bf16); A@B ~= Ah@Bh + Ah@Bl + Al@Bh
// RULE (R4-R9 lesson): NEVER pass __device__ globals as kernel args from host.
// ---------------------------------------------------------------------------

__device__ float g_gelu[1024 * 768];
__device__ __align__(16) __nv_bfloat16 g_pooled_h[1024 * 768];
__device__ __align__(16) __nv_bfloat16 g_pooled_l[1024 * 768];
__device__ __align__(16) __nv_bfloat16 g_wqk_h[8192 * 768];
__device__ __align__(16) __nv_bfloat16 g_wqk_l[8192 * 768];
__device__ __align__(16) __nv_bfloat16 g_wrel_h[4096 * 768];
__device__ __align__(16) __nv_bfloat16 g_wrel_l[4096 * 768];
__device__ __align__(16) __nv_bfloat16 g_rpf_h[1024 * 768];
__device__ __align__(16) __nv_bfloat16 g_rpf_l[1024 * 768];
__device__ __align__(16) __nv_bfloat16 g_qk_h[1024 * 8192];
__device__ __align__(16) __nv_bfloat16 g_qk_l[1024 * 8192];
__device__ __align__(16) __nv_bfloat16 g_re_h[1024 * 4096];
__device__ __align__(16) __nv_bfloat16 g_re_l[1024 * 4096];
__device__ float g_outer[1024 * 256];
__device__ float g_outer_part[6 * 1024 * 256];
__device__ float g_vq[32 * 1024];
__device__ float g_vk[32 * 1024];
__device__ float g_tq_hip[33554432];   // [h][i][p']
__device__ float g_tk_hip[33554432];
__device__ float g_tq_iph[33554432];   // [i][p'][h]
__device__ float g_tk_iph[33554432];
__device__ float g_sim[33554432];      // [h][i][j]

// ---------------------------------------------------------------------------
__global__ void pool_gelu_kernel(const float* __restrict__ single)
{
    const int i = blockIdx.x;
    const int c = threadIdx.x;
    const float* p = single + ((size_t)i * 16) * 768 + c;
    float s = 0.f;
#pragma unroll
    for (int t = 0; t < 16; t++) s += p[t * 768];
    s *= 0.0625f;
    __nv_bfloat16 h = __float2bfloat16(s);
    g_pooled_h[i * 768 + c] = h;
    g_pooled_l[i * 768 + c] = __float2bfloat16(s - __bfloat162float(h));
    g_gelu[i * 768 + c] = 0.5f * s * (1.f + erff(s * 0.7071067811865475f));
}

// Split-convert all weight operands; destinations chosen IN DEVICE CODE.
__global__ void __launch_bounds__(256) convert_all(
    const float* __restrict__ wqk, const float* __restrict__ wrel,
    const float* __restrict__ rpf)
{
    long i = (long)blockIdx.x * 256 + threadIdx.x;
    const float* src;
    __nv_bfloat16 *hi, *lo;
    long o;
    if (i < 6291456L) {
        src = wqk; o = i; hi = g_wqk_h; lo = g_wqk_l;
    } else if (i < 9437184L) {
        src = wrel; o = i - 6291456L; hi = g_wrel_h; lo = g_wrel_l;
    } else {
        src = rpf + 544 * 768; o = i - 9437184L; hi = g_rpf_h; lo = g_rpf_l;
    }
    float v = src[o];
    __nv_bfloat16 h = __float2bfloat16(v);
    hi[o] = h;
    lo[o] = __float2bfloat16(v - __bfloat162float(h));
}

// vq[h][p] = sum_d qb[h][d]*re[p][h*128+d]; vk likewise
__global__ void __launch_bounds__(256) bias_vec(const float* __restrict__ qk_bias)
{
    int idx = blockIdx.x * 256 + threadIdx.x;   // 32768
    int h = idx >> 10, p = idx & 1023;
    const float* qb = qk_bias + h * 128;
    const float* kb = qk_bias + 4096 + h * 128;
    int base = p * 4096 + h * 128;
    float sq = 0.f, sk = 0.f;
#pragma unroll 8
    for (int d = 0; d < 128; d++) {
        float r = __bfloat162float(g_re_h[base + d]) + __bfloat162float(g_re_l[base + d]);
        sq += qb[d] * r;
        sk += kb[d] * r;
    }
    g_vq[idx] = sq;
    g_vk[idx] = sk;
}

// ---------------------------------------------------------------------------
// cp.async helpers (sm_80 baseline PTX)
// ---------------------------------------------------------------------------
__device__ __forceinline__ void cp16(uint32_t dst, const void* src) {
    asm volatile("cp.async.cg.shared.global [%0], [%1], 16;" :: "r"(dst), "l"(src));
}
__device__ __forceinline__ void cp_commit() {
    asm volatile("cp.async.commit_group;" ::: "memory");
}
__device__ __forceinline__ void cp_wait0() {
    asm volatile("cp.async.wait_group 0;" ::: "memory");
}

// ---------------------------------------------------------------------------
// WMMA bf16-split GEMM. 512 threads, 16 warps, warp tile 32x32, block 128x128.
// K-chunk 16, cp.async double buffer (2 x 24KB = 48KB), ONE sync per chunk.
// ---------------------------------------------------------------------------
#define SMS 24
#define ROW_B 48
#define REG_B 6144
#define STAGE_B 24576

__device__ __forceinline__ void stage_cp(uint32_t smbase, int stg,
    const __nv_bfloat16* __restrict__ Ah, const __nv_bfloat16* __restrict__ Al,
    int lda, int bm,
    const __nv_bfloat16* __restrict__ Bh, const __nv_bfloat16* __restrict__ Bl,
    int ldb, int bn, int kofs, int tid)
{
    const uint32_t s0 = smbase + stg * STAGE_B;
    const int grp = tid >> 8;
    const int t = tid & 255;
    const int row = t >> 1, half = t & 1;
    const __nv_bfloat16* pH = grp ? Bh : Ah;
    const __nv_bfloat16* pL = grp ? Bl : Al;
    const int ld = grp ? ldb : lda;
    const int r0 = grp ? bn : bm;
    const size_t off = (size_t)(r0 + row) * ld + kofs + (half << 3);
    const uint32_t d = s0 + grp * (2 * REG_B) + row * ROW_B + (half << 4);
    cp16(d, pH + off);
    cp16(d + REG_B, pL + off);
}

__global__ void __launch_bounds__(512) wmma_gemm(int mode,
    const float* __restrict__ X0)
{
    __shared__ __align__(16) char smbuf[2 * STAGE_B];   // 48KB
    const uint32_t smbase = (uint32_t)__cvta_generic_to_shared(smbuf);

    const int tid = threadIdx.x;
    const int wid = tid >> 5, lane = tid & 31;
    const int wm = (wid & 3) << 5;
    const int wn = (wid >> 2) << 5;
    const int z = blockIdx.z;
    const int bm = blockIdx.y << 7, bn = blockIdx.x << 7;

    const __nv_bfloat16 *Ah, *Al, *Bh, *Bl;
    float* Cf = nullptr;
    __nv_bfloat16 *Ch = nullptr, *Cl = nullptr;
    const float* cb = nullptr;
    int lda, ldb, ldc, K;
    switch (mode) {
    case 0:
        Ah = g_pooled_h; Al = g_pooled_l; lda = 768;
        Bh = g_wqk_h; Bl = g_wqk_l; ldb = 768;
        Ch = g_qk_h; Cl = g_qk_l; ldc = 8192; K = 768; break;
    case 1:
        Ah = g_rpf_h; Al = g_rpf_l; lda = 768;
        Bh = g_wrel_h; Bl = g_wrel_l; ldb = 768;
        Ch = g_re_h; Cl = g_re_l; ldc = 4096; K = 768; cb = X0; break;
    case 3:
        Ah = g_qk_h + z * 128; Al = g_qk_l + z * 128; lda = 8192;
        Bh = g_re_h + z * 128; Bl = g_re_l + z * 128; ldb = 4096;
        Cf = g_tq_hip + ((size_t)z << 20); ldc = 1024; K = 128; cb = g_vq + z * 1024; break;
    case 4:
        Ah = g_qk_h + 4096 + z * 128; Al = g_qk_l + 4096 + z * 128; lda = 8192;
        Bh = g_re_h + z * 128; Bl = g_re_l + z * 128; ldb = 4096;
        Cf = g_tk_hip + ((size_t)z << 20); ldc = 1024; K = 128; cb = g_vk + z * 1024; break;
    default:
        Ah = g_qk_h + z * 128; Al = g_qk_l + z * 128; lda = 8192;
        Bh = g_qk_h + 4096 + z * 128; Bl = g_qk_l + 4096 + z * 128; ldb = 8192;
        Cf = g_sim + ((size_t)z << 20); ldc = 1024; K = 128; break;
    }

    wmma::fragment<wmma::accumulator, 16, 16, 16, float> acc[2][2];
#pragma unroll
    for (int mf = 0; mf < 2; mf++)
#pragma unroll
        for (int nf = 0; nf < 2; nf++) wmma::fill_fragment(acc[mf][nf], 0.f);

    const int nK = K >> 4;

    stage_cp(smbase, 0, Ah, Al, lda, bm, Bh, Bl, ldb, bn, 0, tid);
    cp_commit();

    int cur = 0;
    for (int kc = 0; kc < nK; kc++) {
        cp_wait0();          // stage `cur` landed (this thread's groups)
        __syncthreads();     // publish data; prev compute (reads of cur^1) done
        if (kc + 1 < nK) {   // overlap next stage copy with compute below
            stage_cp(smbase, cur ^ 1, Ah, Al, lda, bm, Bh, Bl, ldb, bn,
                     (kc + 1) << 4, tid);
            cp_commit();
        }

        const __nv_bfloat16* sAh = (const __nv_bfloat16*)(smbuf + cur * STAGE_B);
        const __nv_bfloat16* sAl = (const __nv_bfloat16*)(smbuf + cur * STAGE_B + REG_B);
        const __nv_bfloat16* sBh = (const __nv_bfloat16*)(smbuf + cur * STAGE_B + 2 * REG_B);
        const __nv_bfloat16* sBl = (const __nv_bfloat16*)(smbuf + cur * STAGE_B + 3 * REG_B);

        wmma::fragment<wmma::matrix_a, 16, 16, 16, __nv_bfloat16, wmma::row_major> ah[2], al[2];
        wmma::fragment<wmma::matrix_b, 16, 16, 16, __nv_bfloat16, wmma::col_major> bh[2], bl[2];
#pragma unroll
        for (int mf = 0; mf < 2; mf++) {
            wmma::load_matrix_sync(ah[mf], sAh + (wm + mf * 16) * SMS, SMS);
            wmma::load_matrix_sync(al[mf], sAl + (wm + mf * 16) * SMS, SMS);
        }
#pragma unroll
        for (int nf = 0; nf < 2; nf++) {
            wmma::load_matrix_sync(bh[nf], sBh + (wn + nf * 16) * SMS, SMS);
            wmma::load_matrix_sync(bl[nf], sBl + (wn + nf * 16) * SMS, SMS);
        }
#pragma unroll
        for (int mf = 0; mf < 2; mf++)
#pragma unroll
            for (int nf = 0; nf < 2; nf++) {
                wmma::mma_sync(acc[mf][nf], ah[mf], bh[nf], acc[mf][nf]);
                wmma::mma_sync(acc[mf][nf], ah[mf], bl[nf], acc[mf][nf]);
                wmma::mma_sync(acc[mf][nf], al[mf], bh[nf], acc[mf][nf]);
            }
        cur ^= 1;
    }

    __syncthreads();   // all compute done before scratch aliases smbuf
    float* sc = (float*)smbuf + wid * 256;
    const int rr = lane >> 1;
    const int cc = (lane & 1) << 3;
#pragma unroll
    for (int mf = 0; mf < 2; mf++)
#pragma unroll
        for (int nf = 0; nf < 2; nf++) {
            wmma::store_matrix_sync(sc, acc[mf][nf], 16, wmma::mem_row_major);
            __syncwarp();
            const int row = bm + wm + mf * 16 + rr;
            const int col = bn + wn + nf * 16 + cc;
            float4 v0 = *(float4*)&sc[rr * 16 + cc];
            float4 v1 = *(float4*)&sc[rr * 16 + cc + 4];
            if (cb) {
                const float* b = cb + col;
                v0.x += b[0]; v0.y += b[1]; v0.z += b[2]; v0.w += b[3];
                v1.x += b[4]; v1.y += b[5]; v1.z += b[6]; v1.w += b[7];
            }
            if (Cf) {
                float* op = Cf + (size_t)row * ldc + col;
                *(float4*)op = v0;
                *((float4*)op + 1) = v1;
            } else {
                size_t o = (size_t)row * ldc + col;
                float vv[8] = {v0.x, v0.y, v0.z, v0.w, v1.x, v1.y, v1.z, v1.w};
#pragma unroll
                for (int c2 = 0; c2 < 8; c2 += 2) {
                    __nv_bfloat16 h0 = __float2bfloat16(vv[c2]);
                    __nv_bfloat16 h1 = __float2bfloat16(vv[c2 + 1]);
                    *(__nv_bfloat162*)&Ch[o + c2] = __halves2bfloat162(h0, h1);
                    *(__nv_bfloat162*)&Cl[o + c2] = __halves2bfloat162(
                        __float2bfloat16(vv[c2] - __bfloat162float(h0)),
                        __float2bfloat16(vv[c2 + 1] - __bfloat162float(h1)));
                }
            }
            __syncwarp();
        }
}

// ---------------------------------------------------------------------------
// fp32 SGEMM for outer, split-K (6 x 128) -> partials, then reduce.
// ---------------------------------------------------------------------------
__global__ void __launch_bounds__(256) sgemm_outer_splitk(const float* __restrict__ w_outer)
{
    const int kz = blockIdx.z;
    const float* A = g_gelu + kz * 128;
    const float* B = w_outer + kz * 128;
    float* C = g_outer_part + kz * 262144;
    const int lda = 768, ldb = 768, ldc = 256, K = 128;

    __shared__ float As[8][128];
    __shared__ float Bs[8][128];
    const int tid = threadIdx.x;
    const int bm = blockIdx.y << 7, bn = blockIdx.x << 7;
    const int lrow = tid >> 1;
    const int lk = (tid & 1) << 2;
    const int tr = (tid >> 4) << 3;
    const int tc = (tid & 15) << 3;

    float acc[8][8];
#pragma unroll
    for (int u = 0; u < 8; u++)
#pragma unroll
        for (int v = 0; v < 8; v++) acc[u][v] = 0.f;

    const float* Ap = A + (size_t)(bm + lrow) * lda + lk;
    const float* Bp = B + (size_t)(bn + lrow) * ldb + lk;

    for (int k0 = 0; k0 < K; k0 += 8) {
        float4 av = *(const float4*)(Ap + k0);
        float4 bv = *(const float4*)(Bp + k0);
        As[lk + 0][lrow] = av.x; As[lk + 1][lrow] = av.y;
        As[lk + 2][lrow] = av.z; As[lk + 3][lrow] = av.w;
        Bs[lk + 0][lrow] = bv.x; Bs[lk + 1][lrow] = bv.y;
        Bs[lk + 2][lrow] = bv.z; Bs[lk + 3][lrow] = bv.w;
        __syncthreads();
#pragma unroll
        for (int kk = 0; kk < 8; kk++) {
            float4 a0 = *(const float4*)&As[kk][tr];
            float4 a1 = *(const float4*)&As[kk][tr + 4];
            float4 b0 = *(const float4*)&Bs[kk][tc];
            float4 b1 = *(const float4*)&Bs[kk][tc + 4];
            float ar[8] = {a0.x, a0.y, a0.z, a0.w, a1.x, a1.y, a1.z, a1.w};
            float br[8] = {b0.x, b0.y, b0.z, b0.w, b1.x, b1.y, b1.z, b1.w};
#pragma unroll
            for (int u = 0; u < 8; u++)
#pragma unroll
                for (int v = 0; v < 8; v++) acc[u][v] += ar[u] * br[v];
        }
        __syncthreads();
    }
#pragma unroll
    for (int u = 0; u < 8; u++) {
        float* crow = C + (size_t)(bm + tr + u) * ldc + bn + tc;
        *(float4*)crow = make_float4(acc[u][0], acc[u][1], acc[u][2], acc[u][3]);
        *((float4*)crow + 1) = make_float4(acc[u][4], acc[u][5], acc[u][6], acc[u][7]);
    }
}

__global__ void __launch_bounds__(256) reduce_outer()
{
    int idx = blockIdx.x * 256 + threadIdx.x;
    float s = 0.f;
#pragma unroll
    for (int z = 0; z < 6; z++) s += g_outer_part[z * 262144 + idx];
    g_outer[idx] = s;
}

// ---------------------------------------------------------------------------
// [h][i][p'] -> [i][p'][h]
// ---------------------------------------------------------------------------
__global__ void __launch_bounds__(256) transpose_t()
{
    const float* in = blockIdx.z ? g_tk_hip : g_tq_hip;
    float* o = blockIdx.z ? g_tk_iph : g_tq_iph;
    __shared__ float s[32][65];
    const int i = blockIdx.y;
    const int p0 = blockIdx.x << 6;
    const int tid = threadIdx.x;
    for (int idx = tid; idx < 2048; idx += 256) {
        int h = idx >> 6, p = idx & 63;
        s[h][p] = in[((size_t)h << 20) + ((size_t)i << 10) + p0 + p];
    }
    __syncthreads();
    for (int idx = tid; idx < 2048; idx += 256) {
        int p = idx >> 5, h = idx & 31;
        o[(((size_t)i << 10) + p0 + p) * 32 + h] = s[h][p];
    }
}

// ---------------------------------------------------------------------------
// Final fused kernel: gather + WMMA bf16-split 32->128 projection + outer sum.
// smem layout (byte offsets in fsm):
//  TQ 0 (7952) | TK 7952 (8448) | SH 16400 (4608) | SL 21008 (4608)
//  WH 25616 (8704) | WL 34320 (8704) | BO 43024 (512)   total 43536
//  scratch (8 warps x 256 f32 = 8KB) aliases [0, 8192) after gather phase.
// ---------------------------------------------------------------------------
#define F_TQ 0
#define F_TK 7952
#define F_SH 16400
#define F_SL 21008
#define F_WH 25616
#define F_WL 34320
#define F_BO 43024
#define SLD 72      // s tile ld (bf16 elems), col-major A
#define WLD 136     // w_pair tile ld (bf16 elems), row-major B

__global__ void __launch_bounds__(256) final_kernel(
    const float* __restrict__ w_pair, const float* __restrict__ b_pair,
    float* __restrict__ out)
{
    __shared__ __align__(16) char fsm[43536];
    float* s_tq = (float*)(fsm + F_TQ);
    float* s_tk = (float*)(fsm + F_TK);          // [64][33]
    __nv_bfloat16* s_h = (__nv_bfloat16*)(fsm + F_SH);
    __nv_bfloat16* s_l = (__nv_bfloat16*)(fsm + F_SL);
    __nv_bfloat16* w_h = (__nv_bfloat16*)(fsm + F_WH);
    __nv_bfloat16* w_l = (__nv_bfloat16*)(fsm + F_WL);
    float* s_bo = (float*)(fsm + F_BO);

    const int i = blockIdx.y;
    const int j0 = blockIdx.x << 6;
    const int tid = threadIdx.x;
    const int wid = tid >> 5, lane = tid & 31;

    // w_pair[c][h] -> split [h][c]
    for (int idx = tid; idx < 4096; idx += 256) {
        float v = w_pair[idx];
        int c = idx >> 5, h = idx & 31;
        __nv_bfloat16 hh = __float2bfloat16(v);
        w_h[h * WLD + c] = hh;
        w_l[h * WLD + c] = __float2bfloat16(v - __bfloat162float(hh));
    }
    if (tid < 128) s_bo[tid] = b_pair[tid] + g_outer[i * 256 + tid];

    const int F0 = 18432 + (j0 << 5);
    const int f0 = F0 - F0 / 33 - 17409;
    {
        const float* tqb = g_tq_iph + ((size_t)i << 15) + f0;
        for (int idx = tid; idx < 1988; idx += 256) s_tq[idx] = tqb[idx];
    }
    const int M0 = 18432 + (i << 5);
    const int gb = M0 - M0 / 33 - 17409;
    for (int idx = tid; idx < 2048; idx += 256) {
        int jj = idx >> 5, x = idx & 31;
        s_tk[jj * 33 + x] = g_tk_iph[((size_t)(j0 + jj) << 15) + gb + x];
    }
    __syncthreads();

    // combined s = sim + 0.5*(tq+tk), split to bf16 hi/lo [h][jj]
    for (int idx = tid; idx < 2048; idx += 256) {
        int h = idx >> 6, jj = idx & 63;
        float sv = g_sim[((size_t)h << 20) + ((size_t)i << 10) + (j0 + jj)];
        int m = F0 + (jj << 5) + h;
        int P = m / 33, r = m - P * 33;
        float tq = (r == 0) ? 0.f : s_tq[m - P - 17409 - f0];
        int mi = M0 + h;
        int Pi = mi / 33, ri = mi - Pi * 33;
        float tk = (ri == 0) ? 0.f : s_tk[jj * 33 + (mi - Pi - 17409 - gb)];
        sv += 0.5f * (tq + tk);
        __nv_bfloat16 hh = __float2bfloat16(sv);
        s_h[h * SLD + jj] = hh;
        s_l[h * SLD + jj] = __float2bfloat16(sv - __bfloat162float(hh));
    }
    __syncthreads();   // s/w tiles ready; s_tq/s_tk now dead (scratch aliases)

    // out_tile[jj][c] = sum_h s[h][jj] * wp[h][c]   (64x128, K=32)
    // warp tile 16jj x 16c x4 ; warps: 4 row-groups x 2 col-halves
    const int wm2 = (wid & 3) << 4;
    const int wn2 = (wid >> 2) << 6;
    wmma::fragment<wmma::accumulator, 16, 16, 16, float> acc2[4];
#pragma unroll
    for (int nf = 0; nf < 4; nf++) wmma::fill_fragment(acc2[nf], 0.f);

#pragma unroll
    for (int ks = 0; ks < 2; ks++) {
        const int kb = ks << 4;
        wmma::fragment<wmma::matrix_a, 16, 16, 16, __nv_bfloat16, wmma::col_major> a_h, a_l;
        wmma::load_matrix_sync(a_h, s_h + kb * SLD + wm2, SLD);
        wmma::load_matrix_sync(a_l, s_l + kb * SLD + wm2, SLD);
#pragma unroll
        for (int nf = 0; nf < 4; nf++) {
            wmma::fragment<wmma::matrix_b, 16, 16, 16, __nv_bfloat16, wmma::row_major> b_h, b_l;
            wmma::load_matrix_sync(b_h, w_h + kb * WLD + wn2 + nf * 16, WLD);
            wmma::load_matrix_sync(b_l, w_l + kb * WLD + wn2 + nf * 16, WLD);
            wmma::mma_sync(acc2[nf], a_h, b_h, acc2[nf]);
            wmma::mma_sync(acc2[nf], a_h, b_l, acc2[nf]);
            wmma::mma_sync(acc2[nf], a_l, b_h, acc2[nf]);
        }
    }

    // epilogue: scratch aliased over [0, 8192)
    float* sc = (float*)fsm + wid * 256;
    const int rr = lane >> 1;
    const int cc = (lane & 1) << 3;
    const int j = j0 + wm2 + rr;
#pragma unroll
    for (int nf = 0; nf < 4; nf++) {
        wmma::store_matrix_sync(sc, acc2[nf], 16, wmma::mem_row_major);
        __syncwarp();
        const int c = wn2 + nf * 16 + cc;
        float4 v0 = *(float4*)&sc[rr * 16 + cc];
        float4 v1 = *(float4*)&sc[rr * 16 + cc + 4];
        const float* okp = g_outer + j * 256 + 128 + c;
        v0.x += s_bo[c + 0] + okp[0]; v0.y += s_bo[c + 1] + okp[1];
        v0.z += s_bo[c + 2] + okp[2]; v0.w += s_bo[c + 3] + okp[3];
        v1.x += s_bo[c + 4] + okp[4]; v1.y += s_bo[c + 5] + okp[5];
        v1.z += s_bo[c + 6] + okp[6]; v1.w += s_bo[c + 7] + okp[7];
        float* op = out + ((((size_t)i << 10) + j) << 7) + c;
        *(float4*)op = v0;
        *((float4*)op + 1) = v1;
        __syncwarp();
    }
}

// ---------------------------------------------------------------------------
extern "C" void kernel_launch(void* const* d_in, const int* in_sizes, int n_in,
                              void* d_out, int out_size)
{
    (void)in_sizes; (void)n_in; (void)out_size;
    const float* single        = (const float*)d_in[0];
    const float* rel_pos_feats = (const float*)d_in[1];
    const float* w_qk          = (const float*)d_in[2];
    const float* w_outer       = (const float*)d_in[3];
    const float* w_pair        = (const float*)d_in[4];
    const float* b_pair        = (const float*)d_in[5];
    const float* w_rel         = (const float*)d_in[6];
    const float* b_rel         = (const float*)d_in[7];
    const float* qk_bias       = (const float*)d_in[8];
    float* out = (float*)d_out;

    pool_gelu_kernel<<<1024, 768>>>(single);
    convert_all<<<39936, 256>>>(w_qk, w_rel, rel_pos_feats);

    wmma_gemm<<<dim3(64, 8, 1), 512>>>(0, nullptr);   // qk
    wmma_gemm<<<dim3(32, 8, 1), 512>>>(1, b_rel);     // rel_enc
    sgemm_outer_splitk<<<dim3(2, 8, 6), 256>>>(w_outer);
    reduce_outer<<<1024, 256>>>();
    bias_vec<<<128, 256>>>(qk_bias);
    wmma_gemm<<<dim3(8, 8, 32), 512>>>(3, nullptr);   // t_q
    wmma_gemm<<<dim3(8, 8, 32), 512>>>(4, nullptr);   // t_k
    wmma_gemm<<<dim3(8, 8, 32), 512>>>(5, nullptr);   // sim
    transpose_t<<<dim3(16, 1024, 2), 256>>>();
    final_kernel<<<dim3(16, 1024, 1), 256>>>(w_pair, b_pair, out);
}

// round 13
// speedup vs baseline: 1.1193x; 1.1193x over previous
#include <cuda_runtime.h>
#include <cuda_bf16.h>
#include <mma.h>
#include <math.h>
#include <stdint.h>

using namespace nvcuda;

// ---------------------------------------------------------------------------
// SingleToPairwise — WMMA bf16-split GEMM, cp.async double-buffered.
// R13: 64M x 128N block tile, 256 threads, 36.9KB smem -> ~3 CTAs/SM.
// Split precision: x = hi + lo (bf16); A@B ~= Ah@Bh + Ah@Bl + Al@Bh
// RULE (R4-R9 lesson): NEVER pass __device__ globals as kernel args from host.
// ---------------------------------------------------------------------------

__device__ float g_gelu[1024 * 768];
__device__ __align__(16) __nv_bfloat16 g_pooled_h[1024 * 768];
__device__ __align__(16) __nv_bfloat16 g_pooled_l[1024 * 768];
__device__ __align__(16) __nv_bfloat16 g_wqk_h[8192 * 768];
__device__ __align__(16) __nv_bfloat16 g_wqk_l[8192 * 768];
__device__ __align__(16) __nv_bfloat16 g_wrel_h[4096 * 768];
__device__ __align__(16) __nv_bfloat16 g_wrel_l[4096 * 768];
__device__ __align__(16) __nv_bfloat16 g_rpf_h[1024 * 768];
__device__ __align__(16) __nv_bfloat16 g_rpf_l[1024 * 768];
__device__ __align__(16) __nv_bfloat16 g_qk_h[1024 * 8192];
__device__ __align__(16) __nv_bfloat16 g_qk_l[1024 * 8192];
__device__ __align__(16) __nv_bfloat16 g_re_h[1024 * 4096];
__device__ __align__(16) __nv_bfloat16 g_re_l[1024 * 4096];
__device__ float g_outer[1024 * 256];
__device__ float g_outer_part[6 * 1024 * 256];
__device__ float g_vq[32 * 1024];
__device__ float g_vk[32 * 1024];
__device__ float g_tq_hip[33554432];   // [h][i][p']
__device__ float g_tk_hip[33554432];
__device__ float g_tq_iph[33554432];   // [i][p'][h]
__device__ float g_tk_iph[33554432];
__device__ float g_sim[33554432];      // [h][i][j]

// ---------------------------------------------------------------------------
__global__ void pool_gelu_kernel(const float* __restrict__ single)
{
    const int i = blockIdx.x;
    const int c = threadIdx.x;
    const float* p = single + ((size_t)i * 16) * 768 + c;
    float s = 0.f;
#pragma unroll
    for (int t = 0; t < 16; t++) s += p[t * 768];
    s *= 0.0625f;
    __nv_bfloat16 h = __float2bfloat16(s);
    g_pooled_h[i * 768 + c] = h;
    g_pooled_l[i * 768 + c] = __float2bfloat16(s - __bfloat162float(h));
    g_gelu[i * 768 + c] = 0.5f * s * (1.f + erff(s * 0.7071067811865475f));
}

// Split-convert all weight operands; destinations chosen IN DEVICE CODE.
__global__ void __launch_bounds__(256) convert_all(
    const float* __restrict__ wqk, const float* __restrict__ wrel,
    const float* __restrict__ rpf)
{
    long i = (long)blockIdx.x * 256 + threadIdx.x;
    const float* src;
    __nv_bfloat16 *hi, *lo;
    long o;
    if (i < 6291456L) {
        src = wqk; o = i; hi = g_wqk_h; lo = g_wqk_l;
    } else if (i < 9437184L) {
        src = wrel; o = i - 6291456L; hi = g_wrel_h; lo = g_wrel_l;
    } else {
        src = rpf + 544 * 768; o = i - 9437184L; hi = g_rpf_h; lo = g_rpf_l;
    }
    float v = src[o];
    __nv_bfloat16 h = __float2bfloat16(v);
    hi[o] = h;
    lo[o] = __float2bfloat16(v - __bfloat162float(h));
}

// vq[h][p] = sum_d qb[h][d]*re[p][h*128+d]; vk likewise
__global__ void __launch_bounds__(256) bias_vec(const float* __restrict__ qk_bias)
{
    int idx = blockIdx.x * 256 + threadIdx.x;   // 32768
    int h = idx >> 10, p = idx & 1023;
    const float* qb = qk_bias + h * 128;
    const float* kb = qk_bias + 4096 + h * 128;
    int base = p * 4096 + h * 128;
    float sq = 0.f, sk = 0.f;
#pragma unroll 8
    for (int d = 0; d < 128; d++) {
        float r = __bfloat162float(g_re_h[base + d]) + __bfloat162float(g_re_l[base + d]);
        sq += qb[d] * r;
        sk += kb[d] * r;
    }
    g_vq[idx] = sq;
    g_vk[idx] = sk;
}

// ---------------------------------------------------------------------------
// cp.async helpers (sm_80 baseline PTX)
// ---------------------------------------------------------------------------
__device__ __forceinline__ void cp16(uint32_t dst, const void* src) {
    asm volatile("cp.async.cg.shared.global [%0], [%1], 16;" :: "r"(dst), "l"(src));
}
__device__ __forceinline__ void cp_commit() {
    asm volatile("cp.async.commit_group;" ::: "memory");
}
__device__ __forceinline__ void cp_wait1() {
    asm volatile("cp.async.wait_group 1;" ::: "memory");
}
__device__ __forceinline__ void cp_wait0() {
    asm volatile("cp.async.wait_group 0;" ::: "memory");
}

// ---------------------------------------------------------------------------
// WMMA bf16-split GEMM. 256 threads, 8 warps, warp tile 32x32.
// Block tile 64M x 128N, K-chunk 16, cp.async double buffer (2 x 18KB).
// Stage layout: [Ah 3072][Al 3072][Bh 6144][Bl 6144], row stride 48B.
// ---------------------------------------------------------------------------
#define SMS 24
#define ROW_B 48
#define ST_A1 3072
#define ST_B0 6144
#define ST_B1 12288
#define STAGE_B 18432

__device__ __forceinline__ void stage_cp(uint32_t smbase, int stg,
    const __nv_bfloat16* __restrict__ Ah, const __nv_bfloat16* __restrict__ Al,
    int lda, int bm,
    const __nv_bfloat16* __restrict__ Bh, const __nv_bfloat16* __restrict__ Bl,
    int ldb, int bn, int kofs, int tid)
{
    const uint32_t s0 = smbase + stg * STAGE_B;
    // A: 64 rows x 2 chunks x {hi,lo} = 256 ops, one per thread
    {
        const int row = tid >> 2, q = tid & 3;
        const int chunk = q & 1, rg = q >> 1;
        const __nv_bfloat16* p = rg ? Al : Ah;
        const size_t off = (size_t)(bm + row) * lda + kofs + (chunk << 3);
        const uint32_t d = s0 + (rg ? ST_A1 : 0) + row * ROW_B + (chunk << 4);
        cp16(d, p + off);
    }
    // B: 128 rows x 2 chunks x {hi,lo} = 512 ops, two per thread
#pragma unroll
    for (int r = 0; r < 2; r++) {
        const int t = tid + (r << 8);
        const int row = t >> 2, q = t & 3;
        const int chunk = q & 1, rg = q >> 1;
        const __nv_bfloat16* p = rg ? Bl : Bh;
        const size_t off = (size_t)(bn + row) * ldb + kofs + (chunk << 3);
        const uint32_t d = s0 + (rg ? ST_B1 : ST_B0) + row * ROW_B + (chunk << 4);
        cp16(d, p + off);
    }
}

__global__ void __launch_bounds__(256) wmma_gemm(int mode,
    const float* __restrict__ X0)
{
    __shared__ __align__(16) char smbuf[2 * STAGE_B];   // 36864 B
    const uint32_t smbase = (uint32_t)__cvta_generic_to_shared(smbuf);

    const int tid = threadIdx.x;
    const int wid = tid >> 5, lane = tid & 31;
    const int wm = (wid & 1) << 5;      // 0,32
    const int wn = (wid >> 1) << 5;     // 0,32,64,96
    const int z = blockIdx.z;
    const int bm = blockIdx.y << 6, bn = blockIdx.x << 7;

    const __nv_bfloat16 *Ah, *Al, *Bh, *Bl;
    float* Cf = nullptr;
    __nv_bfloat16 *Ch = nullptr, *Cl = nullptr;
    const float* cb = nullptr;
    int lda, ldb, ldc, K;
    switch (mode) {
    case 0:   // qk = pooled @ w_qk^T -> split bf16
        Ah = g_pooled_h; Al = g_pooled_l; lda = 768;
        Bh = g_wqk_h; Bl = g_wqk_l; ldb = 768;
        Ch = g_qk_h; Cl = g_qk_l; ldc = 8192; K = 768; break;
    case 1:   // re = rpf @ w_rel^T + b_rel -> split bf16
        Ah = g_rpf_h; Al = g_rpf_l; lda = 768;
        Bh = g_wrel_h; Bl = g_wrel_l; ldb = 768;
        Ch = g_re_h; Cl = g_re_l; ldc = 4096; K = 768; cb = X0; break;
    case 3:   // t_q[h] = q_h @ re_h^T + vq[h] -> fp32
        Ah = g_qk_h + z * 128; Al = g_qk_l + z * 128; lda = 8192;
        Bh = g_re_h + z * 128; Bl = g_re_l + z * 128; ldb = 4096;
        Cf = g_tq_hip + ((size_t)z << 20); ldc = 1024; K = 128; cb = g_vq + z * 1024; break;
    case 4:   // t_k[h]
        Ah = g_qk_h + 4096 + z * 128; Al = g_qk_l + 4096 + z * 128; lda = 8192;
        Bh = g_re_h + z * 128; Bl = g_re_l + z * 128; ldb = 4096;
        Cf = g_tk_hip + ((size_t)z << 20); ldc = 1024; K = 128; cb = g_vk + z * 1024; break;
    default:  // sim[h] = q_h @ k_h^T -> fp32
        Ah = g_qk_h + z * 128; Al = g_qk_l + z * 128; lda = 8192;
        Bh = g_qk_h + 4096 + z * 128; Bl = g_qk_l + 4096 + z * 128; ldb = 8192;
        Cf = g_sim + ((size_t)z << 20); ldc = 1024; K = 128; break;
    }

    wmma::fragment<wmma::accumulator, 16, 16, 16, float> acc[2][2];
#pragma unroll
    for (int mf = 0; mf < 2; mf++)
#pragma unroll
        for (int nf = 0; nf < 2; nf++) wmma::fill_fragment(acc[mf][nf], 0.f);

    const int nK = K >> 4;

    stage_cp(smbase, 0, Ah, Al, lda, bm, Bh, Bl, ldb, bn, 0, tid);
    cp_commit();

    int cur = 0;
    for (int kc = 0; kc < nK; kc++) {
        const bool more = (kc + 1 < nK);
        if (more) {
            stage_cp(smbase, cur ^ 1, Ah, Al, lda, bm, Bh, Bl, ldb, bn,
                     (kc + 1) << 4, tid);
            cp_commit();
            cp_wait1();
        } else {
            cp_wait0();
        }
        __syncthreads();

        const __nv_bfloat16* sAh = (const __nv_bfloat16*)(smbuf + cur * STAGE_B);
        const __nv_bfloat16* sAl = (const __nv_bfloat16*)(smbuf + cur * STAGE_B + ST_A1);
        const __nv_bfloat16* sBh = (const __nv_bfloat16*)(smbuf + cur * STAGE_B + ST_B0);
        const __nv_bfloat16* sBl = (const __nv_bfloat16*)(smbuf + cur * STAGE_B + ST_B1);

        wmma::fragment<wmma::matrix_a, 16, 16, 16, __nv_bfloat16, wmma::row_major> ah[2], al[2];
        wmma::fragment<wmma::matrix_b, 16, 16, 16, __nv_bfloat16, wmma::col_major> bh[2], bl[2];
#pragma unroll
        for (int mf = 0; mf < 2; mf++) {
            wmma::load_matrix_sync(ah[mf], sAh + (wm + mf * 16) * SMS, SMS);
            wmma::load_matrix_sync(al[mf], sAl + (wm + mf * 16) * SMS, SMS);
        }
#pragma unroll
        for (int nf = 0; nf < 2; nf++) {
            wmma::load_matrix_sync(bh[nf], sBh + (wn + nf * 16) * SMS, SMS);
            wmma::load_matrix_sync(bl[nf], sBl + (wn + nf * 16) * SMS, SMS);
        }
#pragma unroll
        for (int mf = 0; mf < 2; mf++)
#pragma unroll
            for (int nf = 0; nf < 2; nf++) {
                wmma::mma_sync(acc[mf][nf], ah[mf], bh[nf], acc[mf][nf]);
                wmma::mma_sync(acc[mf][nf], ah[mf], bl[nf], acc[mf][nf]);
                wmma::mma_sync(acc[mf][nf], al[mf], bh[nf], acc[mf][nf]);
            }

        __syncthreads();
        cur ^= 1;
    }

    // epilogue via per-warp smem scratch (8 warps x 256 floats = 8KB)
    float* sc = (float*)smbuf + wid * 256;
    const int rr = lane >> 1;
    const int cc = (lane & 1) << 3;
#pragma unroll
    for (int mf = 0; mf < 2; mf++)
#pragma unroll
        for (int nf = 0; nf < 2; nf++) {
            wmma::store_matrix_sync(sc, acc[mf][nf], 16, wmma::mem_row_major);
            __syncwarp();
            const int row = bm + wm + mf * 16 + rr;
            const int col = bn + wn + nf * 16 + cc;
            float4 v0 = *(float4*)&sc[rr * 16 + cc];
            float4 v1 = *(float4*)&sc[rr * 16 + cc + 4];
            if (cb) {
                const float* b = cb + col;
                v0.x += b[0]; v0.y += b[1]; v0.z += b[2]; v0.w += b[3];
                v1.x += b[4]; v1.y += b[5]; v1.z += b[6]; v1.w += b[7];
            }
            if (Cf) {
                float* op = Cf + (size_t)row * ldc + col;
                *(float4*)op = v0;
                *((float4*)op + 1) = v1;
            } else {
                size_t o = (size_t)row * ldc + col;
                float vv[8] = {v0.x, v0.y, v0.z, v0.w, v1.x, v1.y, v1.z, v1.w};
#pragma unroll
                for (int c2 = 0; c2 < 8; c2 += 2) {
                    __nv_bfloat16 h0 = __float2bfloat16(vv[c2]);
                    __nv_bfloat16 h1 = __float2bfloat16(vv[c2 + 1]);
                    *(__nv_bfloat162*)&Ch[o + c2] = __halves2bfloat162(h0, h1);
                    *(__nv_bfloat162*)&Cl[o + c2] = __halves2bfloat162(
                        __float2bfloat16(vv[c2] - __bfloat162float(h0)),
                        __float2bfloat16(vv[c2 + 1] - __bfloat162float(h1)));
                }
            }
            __syncwarp();
        }
}

// ---------------------------------------------------------------------------
// fp32 SGEMM for outer, split-K (6 x 128) -> partials, then reduce.
// ---------------------------------------------------------------------------
__global__ void __launch_bounds__(256) sgemm_outer_splitk(const float* __restrict__ w_outer)
{
    const int kz = blockIdx.z;
    const float* A = g_gelu + kz * 128;
    const float* B = w_outer + kz * 128;
    float* C = g_outer_part + kz * 262144;
    const int lda = 768, ldb = 768, ldc = 256, K = 128;

    __shared__ float As[8][128];
    __shared__ float Bs[8][128];
    const int tid = threadIdx.x;
    const int bm = blockIdx.y << 7, bn = blockIdx.x << 7;
    const int lrow = tid >> 1;
    const int lk = (tid & 1) << 2;
    const int tr = (tid >> 4) << 3;
    const int tc = (tid & 15) << 3;

    float acc[8][8];
#pragma unroll
    for (int u = 0; u < 8; u++)
#pragma unroll
        for (int v = 0; v < 8; v++) acc[u][v] = 0.f;

    const float* Ap = A + (size_t)(bm + lrow) * lda + lk;
    const float* Bp = B + (size_t)(bn + lrow) * ldb + lk;

    for (int k0 = 0; k0 < K; k0 += 8) {
        float4 av = *(const float4*)(Ap + k0);
        float4 bv = *(const float4*)(Bp + k0);
        As[lk + 0][lrow] = av.x; As[lk + 1][lrow] = av.y;
        As[lk + 2][lrow] = av.z; As[lk + 3][lrow] = av.w;
        Bs[lk + 0][lrow] = bv.x; Bs[lk + 1][lrow] = bv.y;
        Bs[lk + 2][lrow] = bv.z; Bs[lk + 3][lrow] = bv.w;
        __syncthreads();
#pragma unroll
        for (int kk = 0; kk < 8; kk++) {
            float4 a0 = *(const float4*)&As[kk][tr];
            float4 a1 = *(const float4*)&As[kk][tr + 4];
            float4 b0 = *(const float4*)&Bs[kk][tc];
            float4 b1 = *(const float4*)&Bs[kk][tc + 4];
            float ar[8] = {a0.x, a0.y, a0.z, a0.w, a1.x, a1.y, a1.z, a1.w};
            float br[8] = {b0.x, b0.y, b0.z, b0.w, b1.x, b1.y, b1.z, b1.w};
#pragma unroll
            for (int u = 0; u < 8; u++)
#pragma unroll
                for (int v = 0; v < 8; v++) acc[u][v] += ar[u] * br[v];
        }
        __syncthreads();
    }
#pragma unroll
    for (int u = 0; u < 8; u++) {
        float* crow = C + (size_t)(bm + tr + u) * ldc + bn + tc;
        *(float4*)crow = make_float4(acc[u][0], acc[u][1], acc[u][2], acc[u][3]);
        *((float4*)crow + 1) = make_float4(acc[u][4], acc[u][5], acc[u][6], acc[u][7]);
    }
}

__global__ void __launch_bounds__(256) reduce_outer()
{
    int idx = blockIdx.x * 256 + threadIdx.x;
    float s = 0.f;
#pragma unroll
    for (int z = 0; z < 6; z++) s += g_outer_part[z * 262144 + idx];
    g_outer[idx] = s;
}

// ---------------------------------------------------------------------------
// [h][i][p'] -> [i][p'][h]
// ---------------------------------------------------------------------------
__global__ void __launch_bounds__(256) transpose_t()
{
    const float* in = blockIdx.z ? g_tk_hip : g_tq_hip;
    float* o = blockIdx.z ? g_tk_iph : g_tq_iph;
    __shared__ float s[32][65];
    const int i = blockIdx.y;
    const int p0 = blockIdx.x << 6;
    const int tid = threadIdx.x;
    for (int idx = tid; idx < 2048; idx += 256) {
        int h = idx >> 6, p = idx & 63;
        s[h][p] = in[((size_t)h << 20) + ((size_t)i << 10) + p0 + p];
    }
    __syncthreads();
    for (int idx = tid; idx < 2048; idx += 256) {
        int p = idx >> 5, h = idx & 31;
        o[(((size_t)i << 10) + p0 + p) * 32 + h] = s[h][p];
    }
}

// ---------------------------------------------------------------------------
// Final fused kernel (gather + 32->128 pair projection + outer sum)
// ---------------------------------------------------------------------------
__global__ void __launch_bounds__(256) final_kernel(
    const float* __restrict__ w_pair, const float* __restrict__ b_pair,
    float* __restrict__ out)
{
    const int i = blockIdx.y;
    const int j0 = blockIdx.x << 6;
    __shared__ float s_s[32][64];
    __shared__ float s_wp[32][132];
    __shared__ float s_tq[1988];
    __shared__ float s_tk[64][33];
    __shared__ float s_bo[128];
    const int tid = threadIdx.x;

    for (int idx = tid; idx < 4096; idx += 256) {
        float v = w_pair[idx];
        s_wp[idx & 31][idx >> 5] = v;
    }
    if (tid < 128) s_bo[tid] = b_pair[tid] + g_outer[i * 256 + tid];

    for (int idx = tid; idx < 2048; idx += 256) {
        int h = idx >> 6, jj = idx & 63;
        s_s[h][jj] = g_sim[((size_t)h << 20) + ((size_t)i << 10) + (j0 + jj)];
    }

    const int F0 = 18432 + (j0 << 5);
    const int f0 = F0 - F0 / 33 - 17409;
    {
        const float* tqb = g_tq_iph + ((size_t)i << 15) + f0;
        for (int idx = tid; idx < 1988; idx += 256) s_tq[idx] = tqb[idx];
    }
    const int M0 = 18432 + (i << 5);
    const int gb = M0 - M0 / 33 - 17409;
    for (int idx = tid; idx < 2048; idx += 256) {
        int jj = idx >> 5, x = idx & 31;
        s_tk[jj][x] = g_tk_iph[((size_t)(j0 + jj) << 15) + gb + x];
    }
    __syncthreads();

    for (int idx = tid; idx < 2048; idx += 256) {
        int h = idx >> 6, jj = idx & 63;
        int m = F0 + (jj << 5) + h;
        int P = m / 33, r = m - P * 33;
        float tq = (r == 0) ? 0.f : s_tq[m - P - 17409 - f0];
        int mi = M0 + h;
        int Pi = mi / 33, ri = mi - Pi * 33;
        float tk = (ri == 0) ? 0.f : s_tk[jj][mi - Pi - 17409 - gb];
        s_s[h][jj] += 0.5f * (tq + tk);
    }
    __syncthreads();

    const int tr = (tid >> 4) << 2;
    const int tc = (tid & 15) << 3;
    float acc[4][8];
#pragma unroll
    for (int u = 0; u < 4; u++)
#pragma unroll
        for (int v = 0; v < 8; v++) acc[u][v] = 0.f;

#pragma unroll
    for (int h = 0; h < 32; h++) {
        float4 a0 = *(const float4*)&s_s[h][tr];
        float4 b0 = *(const float4*)&s_wp[h][tc];
        float4 b1 = *(const float4*)&s_wp[h][tc + 4];
        float ar[4] = {a0.x, a0.y, a0.z, a0.w};
        float br[8] = {b0.x, b0.y, b0.z, b0.w, b1.x, b1.y, b1.z, b1.w};
#pragma unroll
        for (int u = 0; u < 4; u++)
#pragma unroll
            for (int v = 0; v < 8; v++) acc[u][v] += ar[u] * br[v];
    }

#pragma unroll
    for (int u = 0; u < 4; u++) {
        const int j = j0 + tr + u;
        const float* okp = g_outer + j * 256 + 128 + tc;
        float4 k0 = *(const float4*)okp;
        float4 k1 = *(const float4*)(okp + 4);
        float4 o0, o1;
        o0.x = acc[u][0] + s_bo[tc + 0] + k0.x;
        o0.y = acc[u][1] + s_bo[tc + 1] + k0.y;
        o0.z = acc[u][2] + s_bo[tc + 2] + k0.z;
        o0.w = acc[u][3] + s_bo[tc + 3] + k0.w;
        o1.x = acc[u][4] + s_bo[tc + 4] + k1.x;
        o1.y = acc[u][5] + s_bo[tc + 5] + k1.y;
        o1.z = acc[u][6] + s_bo[tc + 6] + k1.z;
        o1.w = acc[u][7] + s_bo[tc + 7] + k1.w;
        float* op = out + ((((size_t)i << 10) + j) << 7) + tc;
        *(float4*)op = o0;
        *((float4*)op + 1) = o1;
    }
}

// ---------------------------------------------------------------------------
extern "C" void kernel_launch(void* const* d_in, const int* in_sizes, int n_in,
                              void* d_out, int out_size)
{
    (void)in_sizes; (void)n_in; (void)out_size;
    const float* single        = (const float*)d_in[0];
    const float* rel_pos_feats = (const float*)d_in[1];
    const float* w_qk          = (const float*)d_in[2];
    const float* w_outer       = (const float*)d_in[3];
    const float* w_pair        = (const float*)d_in[4];
    const float* b_pair        = (const float*)d_in[5];
    const float* w_rel         = (const float*)d_in[6];
    const float* b_rel         = (const float*)d_in[7];
    const float* qk_bias       = (const float*)d_in[8];
    float* out = (float*)d_out;

    pool_gelu_kernel<<<1024, 768>>>(single);
    convert_all<<<39936, 256>>>(w_qk, w_rel, rel_pos_feats);

    wmma_gemm<<<dim3(64, 16, 1), 256>>>(0, nullptr);   // qk
    wmma_gemm<<<dim3(32, 16, 1), 256>>>(1, b_rel);     // rel_enc
    sgemm_outer_splitk<<<dim3(2, 8, 6), 256>>>(w_outer);
    reduce_outer<<<1024, 256>>>();
    bias_vec<<<128, 256>>>(qk_bias);
    wmma_gemm<<<dim3(8, 16, 32), 256>>>(3, nullptr);   // t_q
    wmma_gemm<<<dim3(8, 16, 32), 256>>>(4, nullptr);   // t_k
    wmma_gemm<<<dim3(8, 16, 32), 256>>>(5, nullptr);   // sim
    transpose_t<<<dim3(16, 1024, 2), 256>>>();
    final_kernel<<<dim3(16, 1024, 1), 256>>>(w_pair, b_pair, out);
}

// round 14
// speedup vs baseline: 1.1560x; 1.0328x over previous
#include <cuda_runtime.h>
#include <cuda_bf16.h>
#include <mma.h>
#include <math.h>
#include <stdint.h>

using namespace nvcuda;

// ---------------------------------------------------------------------------
// SingleToPairwise — WMMA bf16-split GEMM, cp.async double-buffered.
// R14: t_q transpose eliminated (final reads g_tq_hip directly).
// Split precision: x = hi + lo (bf16); A@B ~= Ah@Bh + Ah@Bl + Al@Bh
// RULE (R4-R9 lesson): NEVER pass __device__ globals as kernel args from host.
// ---------------------------------------------------------------------------

__device__ float g_gelu[1024 * 768];
__device__ __align__(16) __nv_bfloat16 g_pooled_h[1024 * 768];
__device__ __align__(16) __nv_bfloat16 g_pooled_l[1024 * 768];
__device__ __align__(16) __nv_bfloat16 g_wqk_h[8192 * 768];
__device__ __align__(16) __nv_bfloat16 g_wqk_l[8192 * 768];
__device__ __align__(16) __nv_bfloat16 g_wrel_h[4096 * 768];
__device__ __align__(16) __nv_bfloat16 g_wrel_l[4096 * 768];
__device__ __align__(16) __nv_bfloat16 g_rpf_h[1024 * 768];
__device__ __align__(16) __nv_bfloat16 g_rpf_l[1024 * 768];
__device__ __align__(16) __nv_bfloat16 g_qk_h[1024 * 8192];
__device__ __align__(16) __nv_bfloat16 g_qk_l[1024 * 8192];
__device__ __align__(16) __nv_bfloat16 g_re_h[1024 * 4096];
__device__ __align__(16) __nv_bfloat16 g_re_l[1024 * 4096];
__device__ float g_outer[1024 * 256];
__device__ float g_outer_part[6 * 1024 * 256];
__device__ float g_vq[32 * 1024];
__device__ float g_vk[32 * 1024];
__device__ float g_tq_hip[33554432];   // [hstore][i][p']
__device__ float g_tk_hip[33554432];   // [hstore][j][p']
__device__ float g_tk_iph[33554432];   // [j][p'][hstore]
__device__ float g_sim[33554432];      // [h][i][j]

// ---------------------------------------------------------------------------
__global__ void pool_gelu_kernel(const float* __restrict__ single)
{
    const int i = blockIdx.x;
    const int c = threadIdx.x;
    const float* p = single + ((size_t)i * 16) * 768 + c;
    float s = 0.f;
#pragma unroll
    for (int t = 0; t < 16; t++) s += p[t * 768];
    s *= 0.0625f;
    __nv_bfloat16 h = __float2bfloat16(s);
    g_pooled_h[i * 768 + c] = h;
    g_pooled_l[i * 768 + c] = __float2bfloat16(s - __bfloat162float(h));
    g_gelu[i * 768 + c] = 0.5f * s * (1.f + erff(s * 0.7071067811865475f));
}

// Split-convert all weight operands; destinations chosen IN DEVICE CODE.
__global__ void __launch_bounds__(256) convert_all(
    const float* __restrict__ wqk, const float* __restrict__ wrel,
    const float* __restrict__ rpf)
{
    long i = (long)blockIdx.x * 256 + threadIdx.x;
    const float* src;
    __nv_bfloat16 *hi, *lo;
    long o;
    if (i < 6291456L) {
        src = wqk; o = i; hi = g_wqk_h; lo = g_wqk_l;
    } else if (i < 9437184L) {
        src = wrel; o = i - 6291456L; hi = g_wrel_h; lo = g_wrel_l;
    } else {
        src = rpf + 544 * 768; o = i - 9437184L; hi = g_rpf_h; lo = g_rpf_l;
    }
    float v = src[o];
    __nv_bfloat16 h = __float2bfloat16(v);
    hi[o] = h;
    lo[o] = __float2bfloat16(v - __bfloat162float(h));
}

// vq[h][p] = sum_d qb[h][d]*re[p][h*128+d]; vk likewise
__global__ void __launch_bounds__(256) bias_vec(const float* __restrict__ qk_bias)
{
    int idx = blockIdx.x * 256 + threadIdx.x;   // 32768
    int h = idx >> 10, p = idx & 1023;
    const float* qb = qk_bias + h * 128;
    const float* kb = qk_bias + 4096 + h * 128;
    int base = p * 4096 + h * 128;
    float sq = 0.f, sk = 0.f;
#pragma unroll 8
    for (int d = 0; d < 128; d++) {
        float r = __bfloat162float(g_re_h[base + d]) + __bfloat162float(g_re_l[base + d]);
        sq += qb[d] * r;
        sk += kb[d] * r;
    }
    g_vq[idx] = sq;
    g_vk[idx] = sk;
}

// ---------------------------------------------------------------------------
// cp.async helpers (sm_80 baseline PTX)
// ---------------------------------------------------------------------------
__device__ __forceinline__ void cp16(uint32_t dst, const void* src) {
    asm volatile("cp.async.cg.shared.global [%0], [%1], 16;" :: "r"(dst), "l"(src));
}
__device__ __forceinline__ void cp_commit() {
    asm volatile("cp.async.commit_group;" ::: "memory");
}
__device__ __forceinline__ void cp_wait1() {
    asm volatile("cp.async.wait_group 1;" ::: "memory");
}
__device__ __forceinline__ void cp_wait0() {
    asm volatile("cp.async.wait_group 0;" ::: "memory");
}

// ---------------------------------------------------------------------------
// WMMA bf16-split GEMM. 256 threads, 8 warps, warp tile 32x32.
// Block tile 64M x 128N, K-chunk 16, cp.async double buffer (2 x 18KB).
// ---------------------------------------------------------------------------
#define SMS 24
#define ROW_B 48
#define ST_A1 3072
#define ST_B0 6144
#define ST_B1 12288
#define STAGE_B 18432

__device__ __forceinline__ void stage_cp(uint32_t smbase, int stg,
    const __nv_bfloat16* __restrict__ Ah, const __nv_bfloat16* __restrict__ Al,
    int lda, int bm,
    const __nv_bfloat16* __restrict__ Bh, const __nv_bfloat16* __restrict__ Bl,
    int ldb, int bn, int kofs, int tid)
{
    const uint32_t s0 = smbase + stg * STAGE_B;
    {
        const int row = tid >> 2, q = tid & 3;
        const int chunk = q & 1, rg = q >> 1;
        const __nv_bfloat16* p = rg ? Al : Ah;
        const size_t off = (size_t)(bm + row) * lda + kofs + (chunk << 3);
        const uint32_t d = s0 + (rg ? ST_A1 : 0) + row * ROW_B + (chunk << 4);
        cp16(d, p + off);
    }
#pragma unroll
    for (int r = 0; r < 2; r++) {
        const int t = tid + (r << 8);
        const int row = t >> 2, q = t & 3;
        const int chunk = q & 1, rg = q >> 1;
        const __nv_bfloat16* p = rg ? Bl : Bh;
        const size_t off = (size_t)(bn + row) * ldb + kofs + (chunk << 3);
        const uint32_t d = s0 + (rg ? ST_B1 : ST_B0) + row * ROW_B + (chunk << 4);
        cp16(d, p + off);
    }
}

__global__ void __launch_bounds__(256) wmma_gemm(int mode,
    const float* __restrict__ X0)
{
    __shared__ __align__(16) char smbuf[2 * STAGE_B];   // 36864 B
    const uint32_t smbase = (uint32_t)__cvta_generic_to_shared(smbuf);

    const int tid = threadIdx.x;
    const int wid = tid >> 5, lane = tid & 31;
    const int wm = (wid & 1) << 5;
    const int wn = (wid >> 1) << 5;
    const int z = blockIdx.z;
    const int bm = blockIdx.y << 6, bn = blockIdx.x << 7;

    const __nv_bfloat16 *Ah, *Al, *Bh, *Bl;
    float* Cf = nullptr;
    __nv_bfloat16 *Ch = nullptr, *Cl = nullptr;
    const float* cb = nullptr;
    int lda, ldb, ldc, K;
    switch (mode) {
    case 0:
        Ah = g_pooled_h; Al = g_pooled_l; lda = 768;
        Bh = g_wqk_h; Bl = g_wqk_l; ldb = 768;
        Ch = g_qk_h; Cl = g_qk_l; ldc = 8192; K = 768; break;
    case 1:
        Ah = g_rpf_h; Al = g_rpf_l; lda = 768;
        Bh = g_wrel_h; Bl = g_wrel_l; ldb = 768;
        Ch = g_re_h; Cl = g_re_l; ldc = 4096; K = 768; cb = X0; break;
    case 3:
        Ah = g_qk_h + z * 128; Al = g_qk_l + z * 128; lda = 8192;
        Bh = g_re_h + z * 128; Bl = g_re_l + z * 128; ldb = 4096;
        Cf = g_tq_hip + ((size_t)z << 20); ldc = 1024; K = 128; cb = g_vq + z * 1024; break;
    case 4:
        Ah = g_qk_h + 4096 + z * 128; Al = g_qk_l + 4096 + z * 128; lda = 8192;
        Bh = g_re_h + z * 128; Bl = g_re_l + z * 128; ldb = 4096;
        Cf = g_tk_hip + ((size_t)z << 20); ldc = 1024; K = 128; cb = g_vk + z * 1024; break;
    default:
        Ah = g_qk_h + z * 128; Al = g_qk_l + z * 128; lda = 8192;
        Bh = g_qk_h + 4096 + z * 128; Bl = g_qk_l + 4096 + z * 128; ldb = 8192;
        Cf = g_sim + ((size_t)z << 20); ldc = 1024; K = 128; break;
    }

    wmma::fragment<wmma::accumulator, 16, 16, 16, float> acc[2][2];
#pragma unroll
    for (int mf = 0; mf < 2; mf++)
#pragma unroll
        for (int nf = 0; nf < 2; nf++) wmma::fill_fragment(acc[mf][nf], 0.f);

    const int nK = K >> 4;

    stage_cp(smbase, 0, Ah, Al, lda, bm, Bh, Bl, ldb, bn, 0, tid);
    cp_commit();

    int cur = 0;
    for (int kc = 0; kc < nK; kc++) {
        const bool more = (kc + 1 < nK);
        if (more) {
            stage_cp(smbase, cur ^ 1, Ah, Al, lda, bm, Bh, Bl, ldb, bn,
                     (kc + 1) << 4, tid);
            cp_commit();
            cp_wait1();
        } else {
            cp_wait0();
        }
        __syncthreads();

        const __nv_bfloat16* sAh = (const __nv_bfloat16*)(smbuf + cur * STAGE_B);
        const __nv_bfloat16* sAl = (const __nv_bfloat16*)(smbuf + cur * STAGE_B + ST_A1);
        const __nv_bfloat16* sBh = (const __nv_bfloat16*)(smbuf + cur * STAGE_B + ST_B0);
        const __nv_bfloat16* sBl = (const __nv_bfloat16*)(smbuf + cur * STAGE_B + ST_B1);

        wmma::fragment<wmma::matrix_a, 16, 16, 16, __nv_bfloat16, wmma::row_major> ah[2], al[2];
        wmma::fragment<wmma::matrix_b, 16, 16, 16, __nv_bfloat16, wmma::col_major> bh[2], bl[2];
#pragma unroll
        for (int mf = 0; mf < 2; mf++) {
            wmma::load_matrix_sync(ah[mf], sAh + (wm + mf * 16) * SMS, SMS);
            wmma::load_matrix_sync(al[mf], sAl + (wm + mf * 16) * SMS, SMS);
        }
#pragma unroll
        for (int nf = 0; nf < 2; nf++) {
            wmma::load_matrix_sync(bh[nf], sBh + (wn + nf * 16) * SMS, SMS);
            wmma::load_matrix_sync(bl[nf], sBl + (wn + nf * 16) * SMS, SMS);
        }
#pragma unroll
        for (int mf = 0; mf < 2; mf++)
#pragma unroll
            for (int nf = 0; nf < 2; nf++) {
                wmma::mma_sync(acc[mf][nf], ah[mf], bh[nf], acc[mf][nf]);
                wmma::mma_sync(acc[mf][nf], ah[mf], bl[nf], acc[mf][nf]);
                wmma::mma_sync(acc[mf][nf], al[mf], bh[nf], acc[mf][nf]);
            }

        __syncthreads();
        cur ^= 1;
    }

    float* sc = (float*)smbuf + wid * 256;
    const int rr = lane >> 1;
    const int cc = (lane & 1) << 3;
#pragma unroll
    for (int mf = 0; mf < 2; mf++)
#pragma unroll
        for (int nf = 0; nf < 2; nf++) {
            wmma::store_matrix_sync(sc, acc[mf][nf], 16, wmma::mem_row_major);
            __syncwarp();
            const int row = bm + wm + mf * 16 + rr;
            const int col = bn + wn + nf * 16 + cc;
            float4 v0 = *(float4*)&sc[rr * 16 + cc];
            float4 v1 = *(float4*)&sc[rr * 16 + cc + 4];
            if (cb) {
                const float* b = cb + col;
                v0.x += b[0]; v0.y += b[1]; v0.z += b[2]; v0.w += b[3];
                v1.x += b[4]; v1.y += b[5]; v1.z += b[6]; v1.w += b[7];
            }
            if (Cf) {
                float* op = Cf + (size_t)row * ldc + col;
                *(float4*)op = v0;
                *((float4*)op + 1) = v1;
            } else {
                size_t o = (size_t)row * ldc + col;
                float vv[8] = {v0.x, v0.y, v0.z, v0.w, v1.x, v1.y, v1.z, v1.w};
#pragma unroll
                for (int c2 = 0; c2 < 8; c2 += 2) {
                    __nv_bfloat16 h0 = __float2bfloat16(vv[c2]);
                    __nv_bfloat16 h1 = __float2bfloat16(vv[c2 + 1]);
                    *(__nv_bfloat162*)&Ch[o + c2] = __halves2bfloat162(h0, h1);
                    *(__nv_bfloat162*)&Cl[o + c2] = __halves2bfloat162(
                        __float2bfloat16(vv[c2] - __bfloat162float(h0)),
                        __float2bfloat16(vv[c2 + 1] - __bfloat162float(h1)));
                }
            }
            __syncwarp();
        }
}

// ---------------------------------------------------------------------------
// fp32 SGEMM for outer, split-K (6 x 128) -> partials, then reduce.
// ---------------------------------------------------------------------------
__global__ void __launch_bounds__(256) sgemm_outer_splitk(const float* __restrict__ w_outer)
{
    const int kz = blockIdx.z;
    const float* A = g_gelu + kz * 128;
    const float* B = w_outer + kz * 128;
    float* C = g_outer_part + kz * 262144;
    const int lda = 768, ldb = 768, ldc = 256, K = 128;

    __shared__ float As[8][128];
    __shared__ float Bs[8][128];
    const int tid = threadIdx.x;
    const int bm = blockIdx.y << 7, bn = blockIdx.x << 7;
    const int lrow = tid >> 1;
    const int lk = (tid & 1) << 2;
    const int tr = (tid >> 4) << 3;
    const int tc = (tid & 15) << 3;

    float acc[8][8];
#pragma unroll
    for (int u = 0; u < 8; u++)
#pragma unroll
        for (int v = 0; v < 8; v++) acc[u][v] = 0.f;

    const float* Ap = A + (size_t)(bm + lrow) * lda + lk;
    const float* Bp = B + (size_t)(bn + lrow) * ldb + lk;

    for (int k0 = 0; k0 < K; k0 += 8) {
        float4 av = *(const float4*)(Ap + k0);
        float4 bv = *(const float4*)(Bp + k0);
        As[lk + 0][lrow] = av.x; As[lk + 1][lrow] = av.y;
        As[lk + 2][lrow] = av.z; As[lk + 3][lrow] = av.w;
        Bs[lk + 0][lrow] = bv.x; Bs[lk + 1][lrow] = bv.y;
        Bs[lk + 2][lrow] = bv.z; Bs[lk + 3][lrow] = bv.w;
        __syncthreads();
#pragma unroll
        for (int kk = 0; kk < 8; kk++) {
            float4 a0 = *(const float4*)&As[kk][tr];
            float4 a1 = *(const float4*)&As[kk][tr + 4];
            float4 b0 = *(const float4*)&Bs[kk][tc];
            float4 b1 = *(const float4*)&Bs[kk][tc + 4];
            float ar[8] = {a0.x, a0.y, a0.z, a0.w, a1.x, a1.y, a1.z, a1.w};
            float br[8] = {b0.x, b0.y, b0.z, b0.w, b1.x, b1.y, b1.z, b1.w};
#pragma unroll
            for (int u = 0; u < 8; u++)
#pragma unroll
                for (int v = 0; v < 8; v++) acc[u][v] += ar[u] * br[v];
        }
        __syncthreads();
    }
#pragma unroll
    for (int u = 0; u < 8; u++) {
        float* crow = C + (size_t)(bm + tr + u) * ldc + bn + tc;
        *(float4*)crow = make_float4(acc[u][0], acc[u][1], acc[u][2], acc[u][3]);
        *((float4*)crow + 1) = make_float4(acc[u][4], acc[u][5], acc[u][6], acc[u][7]);
    }
}

__global__ void __launch_bounds__(256) reduce_outer()
{
    int idx = blockIdx.x * 256 + threadIdx.x;
    float s = 0.f;
#pragma unroll
    for (int z = 0; z < 6; z++) s += g_outer_part[z * 262144 + idx];
    g_outer[idx] = s;
}

// ---------------------------------------------------------------------------
// t_k only: [h][j][p'] -> [j][p'][h]
// ---------------------------------------------------------------------------
__global__ void __launch_bounds__(256) transpose_t()
{
    __shared__ float s[32][65];
    const int i = blockIdx.y;
    const int p0 = blockIdx.x << 6;
    const int tid = threadIdx.x;
    for (int idx = tid; idx < 2048; idx += 256) {
        int h = idx >> 6, p = idx & 63;
        s[h][p] = g_tk_hip[((size_t)h << 20) + ((size_t)i << 10) + p0 + p];
    }
    __syncthreads();
    for (int idx = tid; idx < 2048; idx += 256) {
        int p = idx >> 5, h = idx & 31;
        g_tk_iph[(((size_t)i << 10) + p0 + p) * 32 + h] = s[h][p];
    }
}

// ---------------------------------------------------------------------------
// Final fused kernel (gather + 32->128 pair projection + outer sum)
// t_q read directly from g_tq_hip [hstore][i][p'] (no transpose needed).
// ---------------------------------------------------------------------------
__global__ void __launch_bounds__(256) final_kernel(
    const float* __restrict__ w_pair, const float* __restrict__ b_pair,
    float* __restrict__ out)
{
    const int i = blockIdx.y;
    const int j0 = blockIdx.x << 6;
    __shared__ float s_s[32][64];
    __shared__ float s_wp[32][132];
    __shared__ float s_tq[32][64];    // [hstore][x], x = p' - p0
    __shared__ float s_tk[64][33];
    __shared__ float s_bo[128];
    const int tid = threadIdx.x;

    for (int idx = tid; idx < 4096; idx += 256) {
        float v = w_pair[idx];
        s_wp[idx & 31][idx >> 5] = v;
    }
    if (tid < 128) s_bo[tid] = b_pair[tid] + g_outer[i * 256 + tid];

    for (int idx = tid; idx < 2048; idx += 256) {
        int h = idx >> 6, jj = idx & 63;
        s_s[h][jj] = g_sim[((size_t)h << 20) + ((size_t)i << 10) + (j0 + jj)];
    }

    const int F0 = 18432 + (j0 << 5);
    const int p0 = F0 / 33 - 544;            // window start, in [14, 945]
    for (int idx = tid; idx < 2048; idx += 256) {
        int hs = idx >> 6, x = idx & 63;
        s_tq[hs][x] = g_tq_hip[((size_t)hs << 20) + ((size_t)i << 10) + p0 + x];
    }
    const int M0 = 18432 + (i << 5);
    const int gb = M0 - M0 / 33 - 17409;
    for (int idx = tid; idx < 2048; idx += 256) {
        int jj = idx >> 5, x = idx & 31;
        s_tk[jj][x] = g_tk_iph[((size_t)(j0 + jj) << 15) + gb + x];
    }
    __syncthreads();

    for (int idx = tid; idx < 2048; idx += 256) {
        int h = idx >> 6, jj = idx & 63;
        int m = F0 + (jj << 5) + h;
        int P = m / 33, r = m - P * 33;
        float tq = (r == 0) ? 0.f : s_tq[r - 1][P - 544 - p0];
        int mi = M0 + h;
        int Pi = mi / 33, ri = mi - Pi * 33;
        float tk = (ri == 0) ? 0.f : s_tk[jj][mi - Pi - 17409 - gb];
        s_s[h][jj] += 0.5f * (tq + tk);
    }
    __syncthreads();

    const int tr = (tid >> 4) << 2;
    const int tc = (tid & 15) << 3;
    float acc[4][8];
#pragma unroll
    for (int u = 0; u < 4; u++)
#pragma unroll
        for (int v = 0; v < 8; v++) acc[u][v] = 0.f;

#pragma unroll
    for (int h = 0; h < 32; h++) {
        float4 a0 = *(const float4*)&s_s[h][tr];
        float4 b0 = *(const float4*)&s_wp[h][tc];
        float4 b1 = *(const float4*)&s_wp[h][tc + 4];
        float ar[4] = {a0.x, a0.y, a0.z, a0.w};
        float br[8] = {b0.x, b0.y, b0.z, b0.w, b1.x, b1.y, b1.z, b1.w};
#pragma unroll
        for (int u = 0; u < 4; u++)
#pragma unroll
            for (int v = 0; v < 8; v++) acc[u][v] += ar[u] * br[v];
    }

#pragma unroll
    for (int u = 0; u < 4; u++) {
        const int j = j0 + tr + u;
        const float* okp = g_outer + j * 256 + 128 + tc;
        float4 k0 = *(const float4*)okp;
        float4 k1 = *(const float4*)(okp + 4);
        float4 o0, o1;
        o0.x = acc[u][0] + s_bo[tc + 0] + k0.x;
        o0.y = acc[u][1] + s_bo[tc + 1] + k0.y;
        o0.z = acc[u][2] + s_bo[tc + 2] + k0.z;
        o0.w = acc[u][3] + s_bo[tc + 3] + k0.w;
        o1.x = acc[u][4] + s_bo[tc + 4] + k1.x;
        o1.y = acc[u][5] + s_bo[tc + 5] + k1.y;
        o1.z = acc[u][6] + s_bo[tc + 6] + k1.z;
        o1.w = acc[u][7] + s_bo[tc + 7] + k1.w;
        float* op = out + ((((size_t)i << 10) + j) << 7) + tc;
        *(float4*)op = o0;
        *((float4*)op + 1) = o1;
    }
}

// ---------------------------------------------------------------------------
extern "C" void kernel_launch(void* const* d_in, const int* in_sizes, int n_in,
                              void* d_out, int out_size)
{
    (void)in_sizes; (void)n_in; (void)out_size;
    const float* single        = (const float*)d_in[0];
    const float* rel_pos_feats = (const float*)d_in[1];
    const float* w_qk          = (const float*)d_in[2];
    const float* w_outer       = (const float*)d_in[3];
    const float* w_pair        = (const float*)d_in[4];
    const float* b_pair        = (const float*)d_in[5];
    const float* w_rel         = (const float*)d_in[6];
    const float* b_rel         = (const float*)d_in[7];
    const float* qk_bias       = (const float*)d_in[8];
    float* out = (float*)d_out;

    pool_gelu_kernel<<<1024, 768>>>(single);
    convert_all<<<39936, 256>>>(w_qk, w_rel, rel_pos_feats);

    wmma_gemm<<<dim3(64, 16, 1), 256>>>(0, nullptr);   // qk
    wmma_gemm<<<dim3(32, 16, 1), 256>>>(1, b_rel);     // rel_enc
    sgemm_outer_splitk<<<dim3(2, 8, 6), 256>>>(w_outer);
    reduce_outer<<<1024, 256>>>();
    bias_vec<<<128, 256>>>(qk_bias);
    wmma_gemm<<<dim3(8, 16, 32), 256>>>(3, nullptr);   // t_q
    wmma_gemm<<<dim3(8, 16, 32), 256>>>(4, nullptr);   // t_k
    wmma_gemm<<<dim3(8, 16, 32), 256>>>(5, nullptr);   // sim
    transpose_t<<<dim3(16, 1024, 1), 256>>>();
    final_kernel<<<dim3(16, 1024, 1), 256>>>(w_pair, b_pair, out);
}

// round 15
// speedup vs baseline: 1.2904x; 1.1163x over previous
#include <cuda_runtime.h>
#include <cuda_bf16.h>
#include <mma.h>
#include <math.h>
#include <stdint.h>

using namespace nvcuda;

// ---------------------------------------------------------------------------
// SingleToPairwise — WMMA bf16-split GEMM, cp.async double-buffered.
// R15: t_k computed pre-transposed (swap A/B in mode 4, row bias) ->
//      no transpose kernels at all; final gathers both t's coalesced.
// Split precision: x = hi + lo (bf16); A@B ~= Ah@Bh + Ah@Bl + Al@Bh
// RULE (R4-R9 lesson): NEVER pass __device__ globals as kernel args from host.
// ---------------------------------------------------------------------------

__device__ float g_gelu[1024 * 768];
__device__ __align__(16) __nv_bfloat16 g_pooled_h[1024 * 768];
__device__ __align__(16) __nv_bfloat16 g_pooled_l[1024 * 768];
__device__ __align__(16) __nv_bfloat16 g_wqk_h[8192 * 768];
__device__ __align__(16) __nv_bfloat16 g_wqk_l[8192 * 768];
__device__ __align__(16) __nv_bfloat16 g_wrel_h[4096 * 768];
__device__ __align__(16) __nv_bfloat16 g_wrel_l[4096 * 768];
__device__ __align__(16) __nv_bfloat16 g_rpf_h[1024 * 768];
__device__ __align__(16) __nv_bfloat16 g_rpf_l[1024 * 768];
__device__ __align__(16) __nv_bfloat16 g_qk_h[1024 * 8192];
__device__ __align__(16) __nv_bfloat16 g_qk_l[1024 * 8192];
__device__ __align__(16) __nv_bfloat16 g_re_h[1024 * 4096];
__device__ __align__(16) __nv_bfloat16 g_re_l[1024 * 4096];
__device__ float g_outer[1024 * 256];
__device__ float g_outer_part[6 * 1024 * 256];
__device__ float g_vq[32 * 1024];
__device__ float g_vk[32 * 1024];
__device__ float g_tq_hip[33554432];   // [hstore][i][p']
__device__ float g_tk_pj[33554432];    // [hstore][p'][j]  (transposed t_k)
__device__ float g_sim[33554432];      // [h][i][j]

// ---------------------------------------------------------------------------
__global__ void pool_gelu_kernel(const float* __restrict__ single)
{
    const int i = blockIdx.x;
    const int c = threadIdx.x;
    const float* p = single + ((size_t)i * 16) * 768 + c;
    float s = 0.f;
#pragma unroll
    for (int t = 0; t < 16; t++) s += p[t * 768];
    s *= 0.0625f;
    __nv_bfloat16 h = __float2bfloat16(s);
    g_pooled_h[i * 768 + c] = h;
    g_pooled_l[i * 768 + c] = __float2bfloat16(s - __bfloat162float(h));
    g_gelu[i * 768 + c] = 0.5f * s * (1.f + erff(s * 0.7071067811865475f));
}

// Split-convert all weight operands; destinations chosen IN DEVICE CODE.
__global__ void __launch_bounds__(256) convert_all(
    const float* __restrict__ wqk, const float* __restrict__ wrel,
    const float* __restrict__ rpf)
{
    long i = (long)blockIdx.x * 256 + threadIdx.x;
    const float* src;
    __nv_bfloat16 *hi, *lo;
    long o;
    if (i < 6291456L) {
        src = wqk; o = i; hi = g_wqk_h; lo = g_wqk_l;
    } else if (i < 9437184L) {
        src = wrel; o = i - 6291456L; hi = g_wrel_h; lo = g_wrel_l;
    } else {
        src = rpf + 544 * 768; o = i - 9437184L; hi = g_rpf_h; lo = g_rpf_l;
    }
    float v = src[o];
    __nv_bfloat16 h = __float2bfloat16(v);
    hi[o] = h;
    lo[o] = __float2bfloat16(v - __bfloat162float(h));
}

// vq[h][p] = sum_d qb[h][d]*re[p][h*128+d]; vk likewise
__global__ void __launch_bounds__(256) bias_vec(const float* __restrict__ qk_bias)
{
    int idx = blockIdx.x * 256 + threadIdx.x;   // 32768
    int h = idx >> 10, p = idx & 1023;
    const float* qb = qk_bias + h * 128;
    const float* kb = qk_bias + 4096 + h * 128;
    int base = p * 4096 + h * 128;
    float sq = 0.f, sk = 0.f;
#pragma unroll 8
    for (int d = 0; d < 128; d++) {
        float r = __bfloat162float(g_re_h[base + d]) + __bfloat162float(g_re_l[base + d]);
        sq += qb[d] * r;
        sk += kb[d] * r;
    }
    g_vq[idx] = sq;
    g_vk[idx] = sk;
}

// ---------------------------------------------------------------------------
// cp.async helpers (sm_80 baseline PTX)
// ---------------------------------------------------------------------------
__device__ __forceinline__ void cp16(uint32_t dst, const void* src) {
    asm volatile("cp.async.cg.shared.global [%0], [%1], 16;" :: "r"(dst), "l"(src));
}
__device__ __forceinline__ void cp_commit() {
    asm volatile("cp.async.commit_group;" ::: "memory");
}
__device__ __forceinline__ void cp_wait1() {
    asm volatile("cp.async.wait_group 1;" ::: "memory");
}
__device__ __forceinline__ void cp_wait0() {
    asm volatile("cp.async.wait_group 0;" ::: "memory");
}

// ---------------------------------------------------------------------------
// WMMA bf16-split GEMM. 256 threads, 8 warps, warp tile 32x32.
// Block tile 64M x 128N, K-chunk 16, cp.async double buffer (2 x 18KB).
// ---------------------------------------------------------------------------
#define SMS 24
#define ROW_B 48
#define ST_A1 3072
#define ST_B0 6144
#define ST_B1 12288
#define STAGE_B 18432

__device__ __forceinline__ void stage_cp(uint32_t smbase, int stg,
    const __nv_bfloat16* __restrict__ Ah, const __nv_bfloat16* __restrict__ Al,
    int lda, int bm,
    const __nv_bfloat16* __restrict__ Bh, const __nv_bfloat16* __restrict__ Bl,
    int ldb, int bn, int kofs, int tid)
{
    const uint32_t s0 = smbase + stg * STAGE_B;
    {
        const int row = tid >> 2, q = tid & 3;
        const int chunk = q & 1, rg = q >> 1;
        const __nv_bfloat16* p = rg ? Al : Ah;
        const size_t off = (size_t)(bm + row) * lda + kofs + (chunk << 3);
        const uint32_t d = s0 + (rg ? ST_A1 : 0) + row * ROW_B + (chunk << 4);
        cp16(d, p + off);
    }
#pragma unroll
    for (int r = 0; r < 2; r++) {
        const int t = tid + (r << 8);
        const int row = t >> 2, q = t & 3;
        const int chunk = q & 1, rg = q >> 1;
        const __nv_bfloat16* p = rg ? Bl : Bh;
        const size_t off = (size_t)(bn + row) * ldb + kofs + (chunk << 3);
        const uint32_t d = s0 + (rg ? ST_B1 : ST_B0) + row * ROW_B + (chunk << 4);
        cp16(d, p + off);
    }
}

__global__ void __launch_bounds__(256) wmma_gemm(int mode,
    const float* __restrict__ X0)
{
    __shared__ __align__(16) char smbuf[2 * STAGE_B];   // 36864 B
    const uint32_t smbase = (uint32_t)__cvta_generic_to_shared(smbuf);

    const int tid = threadIdx.x;
    const int wid = tid >> 5, lane = tid & 31;
    const int wm = (wid & 1) << 5;
    const int wn = (wid >> 1) << 5;
    const int z = blockIdx.z;
    const int bm = blockIdx.y << 6, bn = blockIdx.x << 7;

    const __nv_bfloat16 *Ah, *Al, *Bh, *Bl;
    float* Cf = nullptr;
    __nv_bfloat16 *Ch = nullptr, *Cl = nullptr;
    const float* cb = nullptr;   // per-column bias
    const float* rb = nullptr;   // per-row bias
    int lda, ldb, ldc, K;
    switch (mode) {
    case 0:   // qk = pooled @ w_qk^T -> split bf16
        Ah = g_pooled_h; Al = g_pooled_l; lda = 768;
        Bh = g_wqk_h; Bl = g_wqk_l; ldb = 768;
        Ch = g_qk_h; Cl = g_qk_l; ldc = 8192; K = 768; break;
    case 1:   // re = rpf @ w_rel^T + b_rel -> split bf16
        Ah = g_rpf_h; Al = g_rpf_l; lda = 768;
        Bh = g_wrel_h; Bl = g_wrel_l; ldb = 768;
        Ch = g_re_h; Cl = g_re_l; ldc = 4096; K = 768; cb = X0; break;
    case 3:   // t_q[h] = q_h @ re_h^T + vq[h] -> fp32 [h][i][p']
        Ah = g_qk_h + z * 128; Al = g_qk_l + z * 128; lda = 8192;
        Bh = g_re_h + z * 128; Bl = g_re_l + z * 128; ldb = 4096;
        Cf = g_tq_hip + ((size_t)z << 20); ldc = 1024; K = 128; cb = g_vq + z * 1024; break;
    case 4:   // t_kT[h] = re_h @ k_h^T + vk (row bias) -> fp32 [h][p'][j]
        Ah = g_re_h + z * 128; Al = g_re_l + z * 128; lda = 4096;
        Bh = g_qk_h + 4096 + z * 128; Bl = g_qk_l + 4096 + z * 128; ldb = 8192;
        Cf = g_tk_pj + ((size_t)z << 20); ldc = 1024; K = 128; rb = g_vk + z * 1024; break;
    default:  // sim[h] = q_h @ k_h^T -> fp32
        Ah = g_qk_h + z * 128; Al = g_qk_l + z * 128; lda = 8192;
        Bh = g_qk_h + 4096 + z * 128; Bl = g_qk_l + 4096 + z * 128; ldb = 8192;
        Cf = g_sim + ((size_t)z << 20); ldc = 1024; K = 128; break;
    }

    wmma::fragment<wmma::accumulator, 16, 16, 16, float> acc[2][2];
#pragma unroll
    for (int mf = 0; mf < 2; mf++)
#pragma unroll
        for (int nf = 0; nf < 2; nf++) wmma::fill_fragment(acc[mf][nf], 0.f);

    const int nK = K >> 4;

    stage_cp(smbase, 0, Ah, Al, lda, bm, Bh, Bl, ldb, bn, 0, tid);
    cp_commit();

    int cur = 0;
    for (int kc = 0; kc < nK; kc++) {
        const bool more = (kc + 1 < nK);
        if (more) {
            stage_cp(smbase, cur ^ 1, Ah, Al, lda, bm, Bh, Bl, ldb, bn,
                     (kc + 1) << 4, tid);
            cp_commit();
            cp_wait1();
        } else {
            cp_wait0();
        }
        __syncthreads();

        const __nv_bfloat16* sAh = (const __nv_bfloat16*)(smbuf + cur * STAGE_B);
        const __nv_bfloat16* sAl = (const __nv_bfloat16*)(smbuf + cur * STAGE_B + ST_A1);
        const __nv_bfloat16* sBh = (const __nv_bfloat16*)(smbuf + cur * STAGE_B + ST_B0);
        const __nv_bfloat16* sBl = (const __nv_bfloat16*)(smbuf + cur * STAGE_B + ST_B1);

        wmma::fragment<wmma::matrix_a, 16, 16, 16, __nv_bfloat16, wmma::row_major> ah[2], al[2];
        wmma::fragment<wmma::matrix_b, 16, 16, 16, __nv_bfloat16, wmma::col_major> bh[2], bl[2];
#pragma unroll
        for (int mf = 0; mf < 2; mf++) {
            wmma::load_matrix_sync(ah[mf], sAh + (wm + mf * 16) * SMS, SMS);
            wmma::load_matrix_sync(al[mf], sAl + (wm + mf * 16) * SMS, SMS);
        }
#pragma unroll
        for (int nf = 0; nf < 2; nf++) {
            wmma::load_matrix_sync(bh[nf], sBh + (wn + nf * 16) * SMS, SMS);
            wmma::load_matrix_sync(bl[nf], sBl + (wn + nf * 16) * SMS, SMS);
        }
#pragma unroll
        for (int mf = 0; mf < 2; mf++)
#pragma unroll
            for (int nf = 0; nf < 2; nf++) {
                wmma::mma_sync(acc[mf][nf], ah[mf], bh[nf], acc[mf][nf]);
                wmma::mma_sync(acc[mf][nf], ah[mf], bl[nf], acc[mf][nf]);
                wmma::mma_sync(acc[mf][nf], al[mf], bh[nf], acc[mf][nf]);
            }

        __syncthreads();
        cur ^= 1;
    }

    float* sc = (float*)smbuf + wid * 256;
    const int rr = lane >> 1;
    const int cc = (lane & 1) << 3;
#pragma unroll
    for (int mf = 0; mf < 2; mf++)
#pragma unroll
        for (int nf = 0; nf < 2; nf++) {
            wmma::store_matrix_sync(sc, acc[mf][nf], 16, wmma::mem_row_major);
            __syncwarp();
            const int row = bm + wm + mf * 16 + rr;
            const int col = bn + wn + nf * 16 + cc;
            float4 v0 = *(float4*)&sc[rr * 16 + cc];
            float4 v1 = *(float4*)&sc[rr * 16 + cc + 4];
            if (cb) {
                const float* b = cb + col;
                v0.x += b[0]; v0.y += b[1]; v0.z += b[2]; v0.w += b[3];
                v1.x += b[4]; v1.y += b[5]; v1.z += b[6]; v1.w += b[7];
            }
            if (rb) {
                float rv = rb[row];
                v0.x += rv; v0.y += rv; v0.z += rv; v0.w += rv;
                v1.x += rv; v1.y += rv; v1.z += rv; v1.w += rv;
            }
            if (Cf) {
                float* op = Cf + (size_t)row * ldc + col;
                *(float4*)op = v0;
                *((float4*)op + 1) = v1;
            } else {
                size_t o = (size_t)row * ldc + col;
                float vv[8] = {v0.x, v0.y, v0.z, v0.w, v1.x, v1.y, v1.z, v1.w};
#pragma unroll
                for (int c2 = 0; c2 < 8; c2 += 2) {
                    __nv_bfloat16 h0 = __float2bfloat16(vv[c2]);
                    __nv_bfloat16 h1 = __float2bfloat16(vv[c2 + 1]);
                    *(__nv_bfloat162*)&Ch[o + c2] = __halves2bfloat162(h0, h1);
                    *(__nv_bfloat162*)&Cl[o + c2] = __halves2bfloat162(
                        __float2bfloat16(vv[c2] - __bfloat162float(h0)),
                        __float2bfloat16(vv[c2 + 1] - __bfloat162float(h1)));
                }
            }
            __syncwarp();
        }
}

// ---------------------------------------------------------------------------
// fp32 SGEMM for outer, split-K (6 x 128) -> partials, then reduce.
// ---------------------------------------------------------------------------
__global__ void __launch_bounds__(256) sgemm_outer_splitk(const float* __restrict__ w_outer)
{
    const int kz = blockIdx.z;
    const float* A = g_gelu + kz * 128;
    const float* B = w_outer + kz * 128;
    float* C = g_outer_part + kz * 262144;
    const int lda = 768, ldb = 768, ldc = 256, K = 128;

    __shared__ float As[8][128];
    __shared__ float Bs[8][128];
    const int tid = threadIdx.x;
    const int bm = blockIdx.y << 7, bn = blockIdx.x << 7;
    const int lrow = tid >> 1;
    const int lk = (tid & 1) << 2;
    const int tr = (tid >> 4) << 3;
    const int tc = (tid & 15) << 3;

    float acc[8][8];
#pragma unroll
    for (int u = 0; u < 8; u++)
#pragma unroll
        for (int v = 0; v < 8; v++) acc[u][v] = 0.f;

    const float* Ap = A + (size_t)(bm + lrow) * lda + lk;
    const float* Bp = B + (size_t)(bn + lrow) * ldb + lk;

    for (int k0 = 0; k0 < K; k0 += 8) {
        float4 av = *(const float4*)(Ap + k0);
        float4 bv = *(const float4*)(Bp + k0);
        As[lk + 0][lrow] = av.x; As[lk + 1][lrow] = av.y;
        As[lk + 2][lrow] = av.z; As[lk + 3][lrow] = av.w;
        Bs[lk + 0][lrow] = bv.x; Bs[lk + 1][lrow] = bv.y;
        Bs[lk + 2][lrow] = bv.z; Bs[lk + 3][lrow] = bv.w;
        __syncthreads();
#pragma unroll
        for (int kk = 0; kk < 8; kk++) {
            float4 a0 = *(const float4*)&As[kk][tr];
            float4 a1 = *(const float4*)&As[kk][tr + 4];
            float4 b0 = *(const float4*)&Bs[kk][tc];
            float4 b1 = *(const float4*)&Bs[kk][tc + 4];
            float ar[8] = {a0.x, a0.y, a0.z, a0.w, a1.x, a1.y, a1.z, a1.w};
            float br[8] = {b0.x, b0.y, b0.z, b0.w, b1.x, b1.y, b1.z, b1.w};
#pragma unroll
            for (int u = 0; u < 8; u++)
#pragma unroll
                for (int v = 0; v < 8; v++) acc[u][v] += ar[u] * br[v];
        }
        __syncthreads();
    }
#pragma unroll
    for (int u = 0; u < 8; u++) {
        float* crow = C + (size_t)(bm + tr + u) * ldc + bn + tc;
        *(float4*)crow = make_float4(acc[u][0], acc[u][1], acc[u][2], acc[u][3]);
        *((float4*)crow + 1) = make_float4(acc[u][4], acc[u][5], acc[u][6], acc[u][7]);
    }
}

__global__ void __launch_bounds__(256) reduce_outer()
{
    int idx = blockIdx.x * 256 + threadIdx.x;
    float s = 0.f;
#pragma unroll
    for (int z = 0; z < 6; z++) s += g_outer_part[z * 262144 + idx];
    g_outer[idx] = s;
}

// ---------------------------------------------------------------------------
// Final fused kernel (gather + 32->128 pair projection + outer sum)
// t_q read from g_tq_hip [hstore][i][p'] window; t_k read directly from
// g_tk_pj [hstore][p'][j] — both fully coalesced, no transposes anywhere.
// ---------------------------------------------------------------------------
__global__ void __launch_bounds__(256) final_kernel(
    const float* __restrict__ w_pair, const float* __restrict__ b_pair,
    float* __restrict__ out)
{
    const int i = blockIdx.y;
    const int j0 = blockIdx.x << 6;
    __shared__ float s_s[32][64];
    __shared__ float s_wp[32][132];
    __shared__ float s_tq[32][64];    // [hstore][x], x = p' - p0
    __shared__ float s_bo[128];
    const int tid = threadIdx.x;

    for (int idx = tid; idx < 4096; idx += 256) {
        float v = w_pair[idx];
        s_wp[idx & 31][idx >> 5] = v;
    }
    if (tid < 128) s_bo[tid] = b_pair[tid] + g_outer[i * 256 + tid];

    const int F0 = 18432 + (j0 << 5);
    const int p0 = F0 / 33 - 544;            // window start, in [14, 945]
    for (int idx = tid; idx < 2048; idx += 256) {
        int hs = idx >> 6, x = idx & 63;
        s_tq[hs][x] = g_tq_hip[((size_t)hs << 20) + ((size_t)i << 10) + p0 + x];
    }
    __syncthreads();

    const int M0 = 18432 + (i << 5);
    for (int idx = tid; idx < 2048; idx += 256) {
        int h = idx >> 6, jj = idx & 63;
        float sv = g_sim[((size_t)h << 20) + ((size_t)i << 10) + (j0 + jj)];
        int m = F0 + (jj << 5) + h;
        int P = m / 33, r = m - P * 33;
        float tq = (r == 0) ? 0.f : s_tq[r - 1][P - 544 - p0];
        int mi = M0 + h;
        int Pi = mi / 33, ri = mi - Pi * 33;
        float tk = (ri == 0) ? 0.f
            : g_tk_pj[((size_t)(ri - 1) << 20) + ((size_t)(Pi - 544) << 10) + j0 + jj];
        s_s[h][jj] = sv + 0.5f * (tq + tk);
    }
    __syncthreads();

    const int tr = (tid >> 4) << 2;
    const int tc = (tid & 15) << 3;
    float acc[4][8];
#pragma unroll
    for (int u = 0; u < 4; u++)
#pragma unroll
        for (int v = 0; v < 8; v++) acc[u][v] = 0.f;

#pragma unroll
    for (int h = 0; h < 32; h++) {
        float4 a0 = *(const float4*)&s_s[h][tr];
        float4 b0 = *(const float4*)&s_wp[h][tc];
        float4 b1 = *(const float4*)&s_wp[h][tc + 4];
        float ar[4] = {a0.x, a0.y, a0.z, a0.w};
        float br[8] = {b0.x, b0.y, b0.z, b0.w, b1.x, b1.y, b1.z, b1.w};
#pragma unroll
        for (int u = 0; u < 4; u++)
#pragma unroll
            for (int v = 0; v < 8; v++) acc[u][v] += ar[u] * br[v];
    }

#pragma unroll
    for (int u = 0; u < 4; u++) {
        const int j = j0 + tr + u;
        const float* okp = g_outer + j * 256 + 128 + tc;
        float4 k0 = *(const float4*)okp;
        float4 k1 = *(const float4*)(okp + 4);
        float4 o0, o1;
        o0.x = acc[u][0] + s_bo[tc + 0] + k0.x;
        o0.y = acc[u][1] + s_bo[tc + 1] + k0.y;
        o0.z = acc[u][2] + s_bo[tc + 2] + k0.z;
        o0.w = acc[u][3] + s_bo[tc + 3] + k0.w;
        o1.x = acc[u][4] + s_bo[tc + 4] + k1.x;
        o1.y = acc[u][5] + s_bo[tc + 5] + k1.y;
        o1.z = acc[u][6] + s_bo[tc + 6] + k1.z;
        o1.w = acc[u][7] + s_bo[tc + 7] + k1.w;
        float* op = out + ((((size_t)i << 10) + j) << 7) + tc;
        *(float4*)op = o0;
        *((float4*)op + 1) = o1;
    }
}

// ---------------------------------------------------------------------------
extern "C" void kernel_launch(void* const* d_in, const int* in_sizes, int n_in,
                              void* d_out, int out_size)
{
    (void)in_sizes; (void)n_in; (void)out_size;
    const float* single        = (const float*)d_in[0];
    const float* rel_pos_feats = (const float*)d_in[1];
    const float* w_qk          = (const float*)d_in[2];
    const float* w_outer       = (const float*)d_in[3];
    const float* w_pair        = (const float*)d_in[4];
    const float* b_pair        = (const float*)d_in[5];
    const float* w_rel         = (const float*)d_in[6];
    const float* b_rel         = (const float*)d_in[7];
    const float* qk_bias       = (const float*)d_in[8];
    float* out = (float*)d_out;

    pool_gelu_kernel<<<1024, 768>>>(single);
    convert_all<<<39936, 256>>>(w_qk, w_rel, rel_pos_feats);

    wmma_gemm<<<dim3(64, 16, 1), 256>>>(0, nullptr);   // qk
    wmma_gemm<<<dim3(32, 16, 1), 256>>>(1, b_rel);     // rel_enc
    sgemm_outer_splitk<<<dim3(2, 8, 6), 256>>>(w_outer);
    reduce_outer<<<1024, 256>>>();
    bias_vec<<<128, 256>>>(qk_bias);
    wmma_gemm<<<dim3(8, 16, 32), 256>>>(3, nullptr);   // t_q
    wmma_gemm<<<dim3(8, 16, 32), 256>>>(4, nullptr);   // t_k (transposed out)
    wmma_gemm<<<dim3(8, 16, 32), 256>>>(5, nullptr);   // sim
    final_kernel<<<dim3(16, 1024, 1), 256>>>(w_pair, b_pair, out);
}